// round 8
// baseline (speedup 1.0000x reference)
#include <cuda_runtime.h>
#include <cuda_bf16.h>
#include <cstdint>

#define B_ 4
#define L_ 2048
#define D_ 512
#define H_ 8
#define DH_ 64
#define M_ (B_ * L_)  // 8192

// Scratch (allocation-free rule: __device__ globals)
__device__ float g_qp[M_ * D_];
__device__ float g_kp[M_ * D_];
__device__ float g_vp[M_ * D_];
__device__ float g_oh[M_ * D_];
__device__ float g_rinv[B_ * H_ * L_];
// bf16 hi/lo splits of the projected tensors
__device__ __nv_bfloat16 g_qh[M_ * D_];
__device__ __nv_bfloat16 g_ql[M_ * D_];
__device__ __nv_bfloat16 g_kh[M_ * D_];
__device__ __nv_bfloat16 g_kl[M_ * D_];
__device__ __nv_bfloat16 g_vh[M_ * D_];
__device__ __nv_bfloat16 g_vl[M_ * D_];

// ===========================================================================
// Warp MMA m16n8k16 bf16 -> fp32 (base sm_80+ feature; assembles on sm_103)
// ===========================================================================
__device__ __forceinline__ void mma16816(float* d, const uint32_t* a,
                                         uint32_t b0, uint32_t b1,
                                         const float* c) {
  asm volatile(
      "mma.sync.aligned.m16n8k16.row.col.f32.bf16.bf16.f32 "
      "{%0,%1,%2,%3}, {%4,%5,%6,%7}, {%8,%9}, {%10,%11,%12,%13};"
      : "=f"(d[0]), "=f"(d[1]), "=f"(d[2]), "=f"(d[3])
      : "r"(a[0]), "r"(a[1]), "r"(a[2]), "r"(a[3]), "r"(b0), "r"(b1),
        "f"(c[0]), "f"(c[1]), "f"(c[2]), "f"(c[3]));
}

// ===========================================================================
// GEMM: Y[M,N] = X[M,K] @ W[N,K]^T + bias[N];  M=8192, N=K=512 (SIMT, proven)
// ===========================================================================
__global__ __launch_bounds__(256) void gemm_bias_kernel(
    const float* __restrict__ X, const float* __restrict__ W,
    const float* __restrict__ bias, float* __restrict__ Y) {
  const int K = 512, N = 512;
  __shared__ __align__(16) float Xs[64][20];
  __shared__ __align__(16) float Ws[16][68];

  int bm = blockIdx.x * 64, bn = blockIdx.y * 64;
  int tid = threadIdx.x;
  int ty = tid >> 4, tx = tid & 15;
  int lr = tid >> 2, lc = (tid & 3) * 4;

  float acc[4][4] = {};

  for (int k0 = 0; k0 < K; k0 += 16) {
    float4 xv = *(const float4*)&X[(size_t)(bm + lr) * K + k0 + lc];
    Xs[lr][lc + 0] = xv.x; Xs[lr][lc + 1] = xv.y;
    Xs[lr][lc + 2] = xv.z; Xs[lr][lc + 3] = xv.w;
    float4 wv = *(const float4*)&W[(size_t)(bn + lr) * K + k0 + lc];
    Ws[lc + 0][lr] = wv.x; Ws[lc + 1][lr] = wv.y;
    Ws[lc + 2][lr] = wv.z; Ws[lc + 3][lr] = wv.w;
    __syncthreads();

#pragma unroll
    for (int kk = 0; kk < 16; kk++) {
      float a[4];
#pragma unroll
      for (int i = 0; i < 4; i++) a[i] = Xs[ty * 4 + i][kk];
      float4 bv = *(const float4*)&Ws[kk][tx * 4];
#pragma unroll
      for (int i = 0; i < 4; i++) {
        acc[i][0] += a[i] * bv.x;
        acc[i][1] += a[i] * bv.y;
        acc[i][2] += a[i] * bv.z;
        acc[i][3] += a[i] * bv.w;
      }
    }
    __syncthreads();
  }

  float4 bb = *(const float4*)&bias[bn + tx * 4];
#pragma unroll
  for (int i = 0; i < 4; i++) {
    float4 o;
    o.x = acc[i][0] + bb.x; o.y = acc[i][1] + bb.y;
    o.z = acc[i][2] + bb.z; o.w = acc[i][3] + bb.w;
    *(float4*)&Y[(size_t)(bm + ty * 4 + i) * N + bn + tx * 4] = o;
  }
}

// ===========================================================================
// fp32 -> bf16 hi/lo split (x = hi + lo, lo = bf16(x - hi))
// ===========================================================================
__global__ __launch_bounds__(256) void split_kernel(
    const float* __restrict__ x, __nv_bfloat16* __restrict__ hi,
    __nv_bfloat16* __restrict__ lo) {
  int i = blockIdx.x * 256 + threadIdx.x;
  float4 v = ((const float4*)x)[i];
  __nv_bfloat162 h0, h1, l0, l1;
  h0.x = __float2bfloat16_rn(v.x); h0.y = __float2bfloat16_rn(v.y);
  h1.x = __float2bfloat16_rn(v.z); h1.y = __float2bfloat16_rn(v.w);
  l0.x = __float2bfloat16_rn(v.x - __bfloat162float(h0.x));
  l0.y = __float2bfloat16_rn(v.y - __bfloat162float(h0.y));
  l1.x = __float2bfloat16_rn(v.z - __bfloat162float(h1.x));
  l1.y = __float2bfloat16_rn(v.w - __bfloat162float(h1.y));
  ((__nv_bfloat162*)hi)[i * 2 + 0] = h0;
  ((__nv_bfloat162*)hi)[i * 2 + 1] = h1;
  ((__nv_bfloat162*)lo)[i * 2 + 0] = l0;
  ((__nv_bfloat162*)lo)[i * 2 + 1] = l1;
}

// ===========================================================================
// Warp-MMA attention (FA2-style), bf16x3 split precision.
// Block: 256 threads / 8 warps; 128 q-rows per block; warp owns 16 q-rows.
// Per 64-key tile: S = Q K^T (3 MMA passes); exp in C-fragment layout;
// P fed to PV MMAs directly from registers (C layout == next A layout).
// ===========================================================================
#define PADK 72  // bf16 row stride: 144B -> fragment lds conflict-free

__global__ __launch_bounds__(256) void attn_mma_kernel(
    const int* __restrict__ mask, float* __restrict__ attn_out, int has_attn) {
  __shared__ __nv_bfloat16 Ksh[64][PADK], Ksl[64][PADK];
  __shared__ __nv_bfloat16 Vth[64][PADK], Vtl[64][PADK];
  __shared__ float maskS[64];

  int tid = threadIdx.x, w = tid >> 5, lane = tid & 31;
  int gr = lane >> 2, ck = lane & 3;
  int bh = blockIdx.y, b = bh >> 3, h = bh & 7;
  int q0 = blockIdx.x * 128;
  int qrow = b * L_ + q0 + 16 * w;  // this warp's first q-row (global)

  // Q fragments (hi/lo), resident in registers for the whole kernel.
  uint32_t qh[4][4], ql[4][4];
#pragma unroll
  for (int kc = 0; kc < 4; kc++) {
    size_t r0 = (size_t)(qrow + gr) * D_ + h * DH_ + kc * 16 + 2 * ck;
    size_t r8 = r0 + (size_t)8 * D_;
    qh[kc][0] = *(const uint32_t*)(g_qh + r0);
    qh[kc][1] = *(const uint32_t*)(g_qh + r8);
    qh[kc][2] = *(const uint32_t*)(g_qh + r0 + 8);
    qh[kc][3] = *(const uint32_t*)(g_qh + r8 + 8);
    ql[kc][0] = *(const uint32_t*)(g_ql + r0);
    ql[kc][1] = *(const uint32_t*)(g_ql + r8);
    ql[kc][2] = *(const uint32_t*)(g_ql + r0 + 8);
    ql[kc][3] = *(const uint32_t*)(g_ql + r8 + 8);
  }

  float Oa[8][4] = {};
  float psum0 = 0.f, psum1 = 0.f;

  for (int kt = 0; kt < 32; kt++) {
    int k0 = kt * 64;
    __syncthreads();  // prev tile fully consumed

    // K tiles: row-major [key][d] (exactly mma-B col-major), 4 threads/row.
    {
      int r = tid >> 2, c4 = (tid & 3) * 16;
      const uint4* skh = (const uint4*)(g_kh + (size_t)(b * L_ + k0 + r) * D_ + h * DH_ + c4);
      *(uint4*)&Ksh[r][c4] = skh[0];
      *(uint4*)&Ksh[r][c4 + 8] = skh[1];
      const uint4* skl = (const uint4*)(g_kl + (size_t)(b * L_ + k0 + r) * D_ + h * DH_ + c4);
      *(uint4*)&Ksl[r][c4] = skl[0];
      *(uint4*)&Ksl[r][c4 + 8] = skl[1];
      // V transposed: Vt[d][key]
      int key = tid & 63, arr = (tid >> 6) & 1, dh2 = tid >> 7;  // d half
      const __nv_bfloat16* vsrc =
          (arr ? g_vl : g_vh) + (size_t)(b * L_ + k0 + key) * D_ + h * DH_ + dh2 * 32;
      __nv_bfloat16(*vdst)[PADK] = arr ? Vtl : Vth;
#pragma unroll
      for (int d = 0; d < 32; d++) vdst[dh2 * 32 + d][key] = vsrc[d];
      if (tid < 64) maskS[tid] = -1e9f * (float)mask[b * L_ + k0 + tid];
    }
    __syncthreads();

    // S = Q K^T  (bf16x3: hh + hl + lh)
    float Sa[8][4] = {};
#pragma unroll
    for (int kc = 0; kc < 4; kc++) {
#pragma unroll
      for (int nt = 0; nt < 8; nt++) {
        int kr = 8 * nt + gr, kcol = kc * 16 + 2 * ck;
        uint32_t bh0 = *(const uint32_t*)&Ksh[kr][kcol];
        uint32_t bh1 = *(const uint32_t*)&Ksh[kr][kcol + 8];
        uint32_t bl0 = *(const uint32_t*)&Ksl[kr][kcol];
        uint32_t bl1 = *(const uint32_t*)&Ksl[kr][kcol + 8];
        mma16816(Sa[nt], qh[kc], bh0, bh1, Sa[nt]);
        mma16816(Sa[nt], qh[kc], bl0, bl1, Sa[nt]);
        mma16816(Sa[nt], ql[kc], bh0, bh1, Sa[nt]);
      }
    }

    // exp epilogue in fragment layout; write unnormalized attn
#pragma unroll
    for (int nt = 0; nt < 8; nt++) {
      float2 mk = *(float2*)&maskS[8 * nt + 2 * ck];
      float p0 = __expf(fmaf(Sa[nt][0], 0.125f, mk.x));
      float p1 = __expf(fmaf(Sa[nt][1], 0.125f, mk.y));
      float p2 = __expf(fmaf(Sa[nt][2], 0.125f, mk.x));
      float p3 = __expf(fmaf(Sa[nt][3], 0.125f, mk.y));
      psum0 += p0 + p1; psum1 += p2 + p3;
      Sa[nt][0] = p0; Sa[nt][1] = p1; Sa[nt][2] = p2; Sa[nt][3] = p3;
      if (has_attn) {
        size_t base = (size_t)(bh * L_ + q0 + 16 * w + gr) * L_ + k0 + 8 * nt + 2 * ck;
        *(float2*)&attn_out[base] = make_float2(p0, p1);
        *(float2*)&attn_out[base + (size_t)8 * L_] = make_float2(p2, p3);
      }
    }

    // O += P V  (P from registers: C layout == A layout)
#pragma unroll
    for (int kc = 0; kc < 4; kc++) {
      uint32_t ph[4], pl[4];
#pragma unroll
      for (int half = 0; half < 2; half++) {  // ntile 2kc, 2kc+1 -> a0a1 / a2a3
        float x0 = Sa[2 * kc + half][0], x1 = Sa[2 * kc + half][1];
        float x2 = Sa[2 * kc + half][2], x3 = Sa[2 * kc + half][3];
        __nv_bfloat162 h01 = __floats2bfloat162_rn(x0, x1);
        __nv_bfloat162 h23 = __floats2bfloat162_rn(x2, x3);
        __nv_bfloat162 l01 = __floats2bfloat162_rn(x0 - __bfloat162float(h01.x),
                                                   x1 - __bfloat162float(h01.y));
        __nv_bfloat162 l23 = __floats2bfloat162_rn(x2 - __bfloat162float(h23.x),
                                                   x3 - __bfloat162float(h23.y));
        ph[2 * half + 0] = *(uint32_t*)&h01; ph[2 * half + 1] = *(uint32_t*)&h23;
        pl[2 * half + 0] = *(uint32_t*)&l01; pl[2 * half + 1] = *(uint32_t*)&l23;
      }
#pragma unroll
      for (int nt = 0; nt < 8; nt++) {
        int dr = 8 * nt + gr, kcol = kc * 16 + 2 * ck;
        uint32_t bh0 = *(const uint32_t*)&Vth[dr][kcol];
        uint32_t bh1 = *(const uint32_t*)&Vth[dr][kcol + 8];
        uint32_t bl0 = *(const uint32_t*)&Vtl[dr][kcol];
        uint32_t bl1 = *(const uint32_t*)&Vtl[dr][kcol + 8];
        mma16816(Oa[nt], ph, bh0, bh1, Oa[nt]);
        mma16816(Oa[nt], ph, bl0, bl1, Oa[nt]);
        mma16816(Oa[nt], pl, bh0, bh1, Oa[nt]);
      }
    }
  }

  // Row sums: reduce across the 4 lanes of each quad (same gr, ck varies)
  psum0 += __shfl_xor_sync(0xFFFFFFFF, psum0, 1);
  psum0 += __shfl_xor_sync(0xFFFFFFFF, psum0, 2);
  psum1 += __shfl_xor_sync(0xFFFFFFFF, psum1, 1);
  psum1 += __shfl_xor_sync(0xFFFFFFFF, psum1, 2);
  float inv0 = 1.0f / psum0, inv1 = 1.0f / psum1;
  if (ck == 0) {
    g_rinv[(size_t)bh * L_ + q0 + 16 * w + gr] = inv0;
    g_rinv[(size_t)bh * L_ + q0 + 16 * w + gr + 8] = inv1;
  }

  // O store (scaled)
#pragma unroll
  for (int nt = 0; nt < 8; nt++) {
    size_t base = (size_t)(b * L_ + q0 + 16 * w + gr) * D_ + h * DH_ + 8 * nt + 2 * ck;
    *(float2*)&g_oh[base] = make_float2(Oa[nt][0] * inv0, Oa[nt][1] * inv0);
    *(float2*)&g_oh[base + (size_t)8 * D_] = make_float2(Oa[nt][2] * inv1, Oa[nt][3] * inv1);
  }
}

// ---------------------------------------------------------------------------
// Normalize attn in place: attn[row, :] *= g_rinv[row]
// ---------------------------------------------------------------------------
__global__ __launch_bounds__(256) void norm_attn_kernel(float* __restrict__ attn) {
  size_t idx = ((size_t)blockIdx.x * 256 + threadIdx.x) * 4;
  size_t row = idx >> 11;
  float inv = g_rinv[row];
  float4 v = *(float4*)&attn[idx];
  v.x *= inv; v.y *= inv; v.z *= inv; v.w *= inv;
  *(float4*)&attn[idx] = v;
}

// ---------------------------------------------------------------------------
extern "C" void kernel_launch(void* const* d_in, const int* in_sizes, int n_in,
                              void* d_out, int out_size) {
  const float* q    = (const float*)d_in[0];
  const float* k    = (const float*)d_in[1];
  const float* v    = (const float*)d_in[2];
  const int*   mask = (const int*)d_in[3];
  const float* wq_w = (const float*)d_in[4];
  const float* wq_b = (const float*)d_in[5];
  const float* wk_w = (const float*)d_in[6];
  const float* wk_b = (const float*)d_in[7];
  const float* wv_w = (const float*)d_in[8];
  const float* wv_b = (const float*)d_in[9];
  const float* wo_w = (const float*)d_in[10];
  const float* wo_b = (const float*)d_in[11];
  float* out = (float*)d_out;

  const long long OUT_N  = (long long)M_ * D_;
  const long long ATTN_N = (long long)B_ * H_ * L_ * L_;
  int has_attn = ((long long)out_size >= OUT_N + ATTN_N) ? 1 : 0;
  float* attn = out + OUT_N;

  void *p_qp, *p_kp, *p_vp, *p_oh;
  void *p_qh, *p_ql, *p_kh, *p_kl, *p_vh, *p_vl;
  cudaGetSymbolAddress(&p_qp, g_qp);
  cudaGetSymbolAddress(&p_kp, g_kp);
  cudaGetSymbolAddress(&p_vp, g_vp);
  cudaGetSymbolAddress(&p_oh, g_oh);
  cudaGetSymbolAddress(&p_qh, g_qh);
  cudaGetSymbolAddress(&p_ql, g_ql);
  cudaGetSymbolAddress(&p_kh, g_kh);
  cudaGetSymbolAddress(&p_kl, g_kl);
  cudaGetSymbolAddress(&p_vh, g_vh);
  cudaGetSymbolAddress(&p_vl, g_vl);

  dim3 gg(M_ / 64, D_ / 64);
  gemm_bias_kernel<<<gg, 256>>>(q, wq_w, wq_b, (float*)p_qp);
  gemm_bias_kernel<<<gg, 256>>>(k, wk_w, wk_b, (float*)p_kp);
  gemm_bias_kernel<<<gg, 256>>>(v, wv_w, wv_b, (float*)p_vp);

  int nsb = (M_ * D_) / 4 / 256;  // 4096 blocks
  split_kernel<<<nsb, 256>>>((const float*)p_qp, (__nv_bfloat16*)p_qh, (__nv_bfloat16*)p_ql);
  split_kernel<<<nsb, 256>>>((const float*)p_kp, (__nv_bfloat16*)p_kh, (__nv_bfloat16*)p_kl);
  split_kernel<<<nsb, 256>>>((const float*)p_vp, (__nv_bfloat16*)p_vh, (__nv_bfloat16*)p_vl);

  dim3 ga(L_ / 128, B_ * H_);
  attn_mma_kernel<<<ga, 256>>>(mask, attn, has_attn);

  if (has_attn) {
    norm_attn_kernel<<<(unsigned)(ATTN_N / 4 / 256), 256>>>(attn);
  }

  gemm_bias_kernel<<<gg, 256>>>((const float*)p_oh, wo_w, wo_b, out);
}

// round 10
// speedup vs baseline: 1.4846x; 1.4846x over previous
#include <cuda_runtime.h>
#include <cuda_bf16.h>
#include <cstdint>

#define B_ 4
#define L_ 2048
#define D_ 512
#define H_ 8
#define DH_ 64
#define M_ (B_ * L_)  // 8192

// Scratch (allocation-free rule: __device__ globals)
__device__ float g_oh[M_ * D_];
__device__ float g_rinv[B_ * H_ * L_];
__device__ __nv_bfloat16 g_qh[M_ * D_];
__device__ __nv_bfloat16 g_ql[M_ * D_];
__device__ __nv_bfloat16 g_kh[M_ * D_];
__device__ __nv_bfloat16 g_kl[M_ * D_];
__device__ __nv_bfloat16 g_vh[M_ * D_];
__device__ __nv_bfloat16 g_vl[M_ * D_];

// ===========================================================================
// Warp MMA m16n8k16 bf16 -> fp32 + ldmatrix (base PTX; assembles on sm_103)
// ===========================================================================
__device__ __forceinline__ void mma16816(float* d, const uint32_t* a,
                                         uint32_t b0, uint32_t b1,
                                         const float* c) {
  asm volatile(
      "mma.sync.aligned.m16n8k16.row.col.f32.bf16.bf16.f32 "
      "{%0,%1,%2,%3}, {%4,%5,%6,%7}, {%8,%9}, {%10,%11,%12,%13};"
      : "=f"(d[0]), "=f"(d[1]), "=f"(d[2]), "=f"(d[3])
      : "r"(a[0]), "r"(a[1]), "r"(a[2]), "r"(a[3]), "r"(b0), "r"(b1),
        "f"(c[0]), "f"(c[1]), "f"(c[2]), "f"(c[3]));
}
__device__ __forceinline__ void ldsm_x4(uint32_t* r, uint32_t addr) {
  asm volatile(
      "ldmatrix.sync.aligned.m8n8.x4.shared.b16 {%0,%1,%2,%3}, [%4];"
      : "=r"(r[0]), "=r"(r[1]), "=r"(r[2]), "=r"(r[3]) : "r"(addr));
}
__device__ __forceinline__ void ldsm_x4_t(uint32_t* r, uint32_t addr) {
  asm volatile(
      "ldmatrix.sync.aligned.m8n8.x4.trans.shared.b16 {%0,%1,%2,%3}, [%4];"
      : "=r"(r[0]), "=r"(r[1]), "=r"(r[2]), "=r"(r[3]) : "r"(addr));
}
__device__ __forceinline__ uint32_t smem_u32(const void* p) {
  uint32_t a;
  asm("{ .reg .u64 t; cvta.to.shared.u64 t, %1; cvt.u32.u64 %0, t; }"
      : "=r"(a) : "l"(p));
  return a;
}

// ===========================================================================
// GEMM: Y[M,N] = X[M,K] @ W[N,K]^T + bias[N];  M=8192, N=K=512 (SIMT, proven)
// If hi != null: write bf16 hi/lo split instead of fp32 Y (fused split).
// ===========================================================================
__global__ __launch_bounds__(256) void gemm_bias_kernel(
    const float* __restrict__ X, const float* __restrict__ W,
    const float* __restrict__ bias, float* __restrict__ Y,
    __nv_bfloat16* __restrict__ hi, __nv_bfloat16* __restrict__ lo) {
  const int K = 512, N = 512;
  __shared__ __align__(16) float Xs[64][20];
  __shared__ __align__(16) float Ws[16][68];

  int bm = blockIdx.x * 64, bn = blockIdx.y * 64;
  int tid = threadIdx.x;
  int ty = tid >> 4, tx = tid & 15;
  int lr = tid >> 2, lc = (tid & 3) * 4;

  float acc[4][4] = {};

  for (int k0 = 0; k0 < K; k0 += 16) {
    float4 xv = *(const float4*)&X[(size_t)(bm + lr) * K + k0 + lc];
    Xs[lr][lc + 0] = xv.x; Xs[lr][lc + 1] = xv.y;
    Xs[lr][lc + 2] = xv.z; Xs[lr][lc + 3] = xv.w;
    float4 wv = *(const float4*)&W[(size_t)(bn + lr) * K + k0 + lc];
    Ws[lc + 0][lr] = wv.x; Ws[lc + 1][lr] = wv.y;
    Ws[lc + 2][lr] = wv.z; Ws[lc + 3][lr] = wv.w;
    __syncthreads();

#pragma unroll
    for (int kk = 0; kk < 16; kk++) {
      float a[4];
#pragma unroll
      for (int i = 0; i < 4; i++) a[i] = Xs[ty * 4 + i][kk];
      float4 bv = *(const float4*)&Ws[kk][tx * 4];
#pragma unroll
      for (int i = 0; i < 4; i++) {
        acc[i][0] += a[i] * bv.x;
        acc[i][1] += a[i] * bv.y;
        acc[i][2] += a[i] * bv.z;
        acc[i][3] += a[i] * bv.w;
      }
    }
    __syncthreads();
  }

  float4 bb = *(const float4*)&bias[bn + tx * 4];
#pragma unroll
  for (int i = 0; i < 4; i++) {
    float4 o;
    o.x = acc[i][0] + bb.x; o.y = acc[i][1] + bb.y;
    o.z = acc[i][2] + bb.z; o.w = acc[i][3] + bb.w;
    size_t base = (size_t)(bm + ty * 4 + i) * N + bn + tx * 4;
    if (hi) {
      __nv_bfloat162 h0, h1, l0, l1;
      h0.x = __float2bfloat16_rn(o.x); h0.y = __float2bfloat16_rn(o.y);
      h1.x = __float2bfloat16_rn(o.z); h1.y = __float2bfloat16_rn(o.w);
      l0.x = __float2bfloat16_rn(o.x - __bfloat162float(h0.x));
      l0.y = __float2bfloat16_rn(o.y - __bfloat162float(h0.y));
      l1.x = __float2bfloat16_rn(o.z - __bfloat162float(h1.x));
      l1.y = __float2bfloat16_rn(o.w - __bfloat162float(h1.y));
      *(__nv_bfloat162*)(hi + base) = h0;
      *(__nv_bfloat162*)(hi + base + 2) = h1;
      *(__nv_bfloat162*)(lo + base) = l0;
      *(__nv_bfloat162*)(lo + base + 2) = l1;
    } else {
      *(float4*)&Y[base] = o;
    }
  }
}

// ===========================================================================
// Warp-MMA attention (FA2-style), bf16x3 split precision, ldmatrix operands.
// Block: 256 threads / 8 warps; 128 q-rows; warp owns 16 q-rows.
// K and V both stored NATURALLY [key][d] (coalesced uint4 stores);
// K frags via ldmatrix.x4, V^T frags via ldmatrix.x4.trans.
// ===========================================================================
#define PADK 72  // bf16 row stride: 144 B = 9*16 (LDSM-aligned, conflict-free)

__global__ __launch_bounds__(256) void attn_mma_kernel(
    const int* __restrict__ mask, float* __restrict__ attn_out, int has_attn) {
  __shared__ __nv_bfloat16 Ksh[64][PADK], Ksl[64][PADK];
  __shared__ __nv_bfloat16 Vsh[64][PADK], Vsl[64][PADK];
  __shared__ float maskS[64];

  int tid = threadIdx.x, w = tid >> 5, lane = tid & 31;
  int gr = lane >> 2, ck = lane & 3;
  int bh = blockIdx.y, b = bh >> 3, h = bh & 7;
  int q0 = blockIdx.x * 128;
  int qrow = b * L_ + q0 + 16 * w;

  // Per-lane ldmatrix offsets (elements), excluding the kc/ntp tile bases.
  // K (non-trans): row = (l&7) + ((l>>4)&1)*8, col = ((l>>3)&1)*8
  int krow_l = (lane & 7) + ((lane >> 4) & 1) * 8;
  int kcol_l = ((lane >> 3) & 1) * 8;
  uint32_t koff = (uint32_t)(krow_l * PADK + kcol_l) * 2;
  // V (trans): row(key) = (l&7) + ((l>>3)&1)*8, col(d) = ((l>>4)&1)*8
  int vrow_l = (lane & 7) + ((lane >> 3) & 1) * 8;
  int vcol_l = ((lane >> 4) & 1) * 8;
  uint32_t voff = (uint32_t)(vrow_l * PADK + vcol_l) * 2;

  uint32_t sKh = smem_u32(&Ksh[0][0]), sKl = smem_u32(&Ksl[0][0]);
  uint32_t sVh = smem_u32(&Vsh[0][0]), sVl = smem_u32(&Vsl[0][0]);

  // Q fragments (hi/lo), resident in registers for the whole kernel.
  uint32_t qh[4][4], ql[4][4];
#pragma unroll
  for (int kc = 0; kc < 4; kc++) {
    size_t r0 = (size_t)(qrow + gr) * D_ + h * DH_ + kc * 16 + 2 * ck;
    size_t r8 = r0 + (size_t)8 * D_;
    qh[kc][0] = *(const uint32_t*)(g_qh + r0);
    qh[kc][1] = *(const uint32_t*)(g_qh + r8);
    qh[kc][2] = *(const uint32_t*)(g_qh + r0 + 8);
    qh[kc][3] = *(const uint32_t*)(g_qh + r8 + 8);
    ql[kc][0] = *(const uint32_t*)(g_ql + r0);
    ql[kc][1] = *(const uint32_t*)(g_ql + r8);
    ql[kc][2] = *(const uint32_t*)(g_ql + r0 + 8);
    ql[kc][3] = *(const uint32_t*)(g_ql + r8 + 8);
  }

  float Oa[8][4] = {};
  float psum0 = 0.f, psum1 = 0.f;

  for (int kt = 0; kt < 32; kt++) {
    int k0 = kt * 64;
    __syncthreads();  // prev tile fully consumed

    // K and V tiles, both natural [key][d]: coalesced uint4 stores.
    {
      int r = tid >> 2, c4 = (tid & 3) * 16;
      size_t gbase = (size_t)(b * L_ + k0 + r) * D_ + h * DH_ + c4;
      const uint4* p;
      p = (const uint4*)(g_kh + gbase);
      *(uint4*)&Ksh[r][c4] = p[0]; *(uint4*)&Ksh[r][c4 + 8] = p[1];
      p = (const uint4*)(g_kl + gbase);
      *(uint4*)&Ksl[r][c4] = p[0]; *(uint4*)&Ksl[r][c4 + 8] = p[1];
      p = (const uint4*)(g_vh + gbase);
      *(uint4*)&Vsh[r][c4] = p[0]; *(uint4*)&Vsh[r][c4 + 8] = p[1];
      p = (const uint4*)(g_vl + gbase);
      *(uint4*)&Vsl[r][c4] = p[0]; *(uint4*)&Vsl[r][c4 + 8] = p[1];
      if (tid < 64) maskS[tid] = -1e9f * (float)mask[b * L_ + k0 + tid];
    }
    __syncthreads();

    // S = Q K^T  (bf16x3: hh + hl + lh)
    float Sa[8][4] = {};
#pragma unroll
    for (int kc = 0; kc < 4; kc++) {
#pragma unroll
      for (int ntp = 0; ntp < 4; ntp++) {
        // tile base: keys 16*ntp, d-chunk 16*kc
        uint32_t tb = (uint32_t)(16 * ntp * PADK + 16 * kc) * 2 + koff;
        uint32_t kh4[4], kl4[4];
        ldsm_x4(kh4, sKh + tb);
        ldsm_x4(kl4, sKl + tb);
        mma16816(Sa[2 * ntp], qh[kc], kh4[0], kh4[1], Sa[2 * ntp]);
        mma16816(Sa[2 * ntp + 1], qh[kc], kh4[2], kh4[3], Sa[2 * ntp + 1]);
        mma16816(Sa[2 * ntp], qh[kc], kl4[0], kl4[1], Sa[2 * ntp]);
        mma16816(Sa[2 * ntp + 1], qh[kc], kl4[2], kl4[3], Sa[2 * ntp + 1]);
        mma16816(Sa[2 * ntp], ql[kc], kh4[0], kh4[1], Sa[2 * ntp]);
        mma16816(Sa[2 * ntp + 1], ql[kc], kh4[2], kh4[3], Sa[2 * ntp + 1]);
      }
    }

    // exp epilogue in fragment layout; write unnormalized attn
#pragma unroll
    for (int nt = 0; nt < 8; nt++) {
      float2 mk = *(float2*)&maskS[8 * nt + 2 * ck];
      float p0 = __expf(fmaf(Sa[nt][0], 0.125f, mk.x));
      float p1 = __expf(fmaf(Sa[nt][1], 0.125f, mk.y));
      float p2 = __expf(fmaf(Sa[nt][2], 0.125f, mk.x));
      float p3 = __expf(fmaf(Sa[nt][3], 0.125f, mk.y));
      psum0 += p0 + p1; psum1 += p2 + p3;
      Sa[nt][0] = p0; Sa[nt][1] = p1; Sa[nt][2] = p2; Sa[nt][3] = p3;
      if (has_attn) {
        size_t base = (size_t)(bh * L_ + q0 + 16 * w + gr) * L_ + k0 + 8 * nt + 2 * ck;
        *(float2*)&attn_out[base] = make_float2(p0, p1);
        *(float2*)&attn_out[base + (size_t)8 * L_] = make_float2(p2, p3);
      }
    }

    // O += P V  (P from registers; V^T frags via ldmatrix.trans)
#pragma unroll
    for (int kc = 0; kc < 4; kc++) {
      uint32_t ph[4], pl[4];
#pragma unroll
      for (int half = 0; half < 2; half++) {
        float x0 = Sa[2 * kc + half][0], x1 = Sa[2 * kc + half][1];
        float x2 = Sa[2 * kc + half][2], x3 = Sa[2 * kc + half][3];
        __nv_bfloat162 h01 = __floats2bfloat162_rn(x0, x1);
        __nv_bfloat162 h23 = __floats2bfloat162_rn(x2, x3);
        __nv_bfloat162 l01 = __floats2bfloat162_rn(x0 - __bfloat162float(h01.x),
                                                   x1 - __bfloat162float(h01.y));
        __nv_bfloat162 l23 = __floats2bfloat162_rn(x2 - __bfloat162float(h23.x),
                                                   x3 - __bfloat162float(h23.y));
        ph[2 * half + 0] = *(uint32_t*)&h01; ph[2 * half + 1] = *(uint32_t*)&h23;
        pl[2 * half + 0] = *(uint32_t*)&l01; pl[2 * half + 1] = *(uint32_t*)&l23;
      }
#pragma unroll
      for (int ntp = 0; ntp < 4; ntp++) {
        // tile base: keys 16*kc, d-tile 16*ntp
        uint32_t tb = (uint32_t)(16 * kc * PADK + 16 * ntp) * 2 + voff;
        uint32_t vh4[4], vl4[4];
        ldsm_x4_t(vh4, sVh + tb);
        ldsm_x4_t(vl4, sVl + tb);
        mma16816(Oa[2 * ntp], ph, vh4[0], vh4[1], Oa[2 * ntp]);
        mma16816(Oa[2 * ntp + 1], ph, vh4[2], vh4[3], Oa[2 * ntp + 1]);
        mma16816(Oa[2 * ntp], ph, vl4[0], vl4[1], Oa[2 * ntp]);
        mma16816(Oa[2 * ntp + 1], ph, vl4[2], vl4[3], Oa[2 * ntp + 1]);
        mma16816(Oa[2 * ntp], pl, vh4[0], vh4[1], Oa[2 * ntp]);
        mma16816(Oa[2 * ntp + 1], pl, vh4[2], vh4[3], Oa[2 * ntp + 1]);
      }
    }
  }

  // Row sums: reduce across the 4 lanes of each quad
  psum0 += __shfl_xor_sync(0xFFFFFFFF, psum0, 1);
  psum0 += __shfl_xor_sync(0xFFFFFFFF, psum0, 2);
  psum1 += __shfl_xor_sync(0xFFFFFFFF, psum1, 1);
  psum1 += __shfl_xor_sync(0xFFFFFFFF, psum1, 2);
  float inv0 = 1.0f / psum0, inv1 = 1.0f / psum1;
  if (ck == 0) {
    g_rinv[(size_t)bh * L_ + q0 + 16 * w + gr] = inv0;
    g_rinv[(size_t)bh * L_ + q0 + 16 * w + gr + 8] = inv1;
  }

  // O store (scaled)
#pragma unroll
  for (int nt = 0; nt < 8; nt++) {
    size_t base = (size_t)(b * L_ + q0 + 16 * w + gr) * D_ + h * DH_ + 8 * nt + 2 * ck;
    *(float2*)&g_oh[base] = make_float2(Oa[nt][0] * inv0, Oa[nt][1] * inv0);
    *(float2*)&g_oh[base + (size_t)8 * D_] = make_float2(Oa[nt][2] * inv1, Oa[nt][3] * inv1);
  }
}

// ---------------------------------------------------------------------------
// Normalize attn in place: attn[row, :] *= g_rinv[row]
// ---------------------------------------------------------------------------
__global__ __launch_bounds__(256) void norm_attn_kernel(float* __restrict__ attn) {
  size_t idx = ((size_t)blockIdx.x * 256 + threadIdx.x) * 4;
  size_t row = idx >> 11;
  float inv = g_rinv[row];
  float4 v = *(float4*)&attn[idx];
  v.x *= inv; v.y *= inv; v.z *= inv; v.w *= inv;
  *(float4*)&attn[idx] = v;
}

// ---------------------------------------------------------------------------
extern "C" void kernel_launch(void* const* d_in, const int* in_sizes, int n_in,
                              void* d_out, int out_size) {
  const float* q    = (const float*)d_in[0];
  const float* k    = (const float*)d_in[1];
  const float* v    = (const float*)d_in[2];
  const int*   mask = (const int*)d_in[3];
  const float* wq_w = (const float*)d_in[4];
  const float* wq_b = (const float*)d_in[5];
  const float* wk_w = (const float*)d_in[6];
  const float* wk_b = (const float*)d_in[7];
  const float* wv_w = (const float*)d_in[8];
  const float* wv_b = (const float*)d_in[9];
  const float* wo_w = (const float*)d_in[10];
  const float* wo_b = (const float*)d_in[11];
  float* out = (float*)d_out;

  const long long OUT_N  = (long long)M_ * D_;
  const long long ATTN_N = (long long)B_ * H_ * L_ * L_;
  int has_attn = ((long long)out_size >= OUT_N + ATTN_N) ? 1 : 0;
  float* attn = out + OUT_N;

  void *p_oh, *p_qh, *p_ql, *p_kh, *p_kl, *p_vh, *p_vl;
  cudaGetSymbolAddress(&p_oh, g_oh);
  cudaGetSymbolAddress(&p_qh, g_qh);
  cudaGetSymbolAddress(&p_ql, g_ql);
  cudaGetSymbolAddress(&p_kh, g_kh);
  cudaGetSymbolAddress(&p_kl, g_kl);
  cudaGetSymbolAddress(&p_vh, g_vh);
  cudaGetSymbolAddress(&p_vl, g_vl);

  dim3 gg(M_ / 64, D_ / 64);
  gemm_bias_kernel<<<gg, 256>>>(q, wq_w, wq_b, nullptr,
                                (__nv_bfloat16*)p_qh, (__nv_bfloat16*)p_ql);
  gemm_bias_kernel<<<gg, 256>>>(k, wk_w, wk_b, nullptr,
                                (__nv_bfloat16*)p_kh, (__nv_bfloat16*)p_kl);
  gemm_bias_kernel<<<gg, 256>>>(v, wv_w, wv_b, nullptr,
                                (__nv_bfloat16*)p_vh, (__nv_bfloat16*)p_vl);

  dim3 ga(L_ / 128, B_ * H_);
  attn_mma_kernel<<<ga, 256>>>(mask, attn, has_attn);

  if (has_attn) {
    norm_attn_kernel<<<(unsigned)(ATTN_N / 4 / 256), 256>>>(attn);
  }

  gemm_bias_kernel<<<gg, 256>>>((const float*)p_oh, wo_w, wo_b, out,
                                nullptr, nullptr);
}

// round 13
// speedup vs baseline: 1.7606x; 1.1859x over previous
#include <cuda_runtime.h>
#include <cuda_bf16.h>
#include <cstdint>

#define B_ 4
#define L_ 2048
#define D_ 512
#define H_ 8
#define DH_ 64
#define M_ (B_ * L_)  // 8192

// Scratch (allocation-free rule: __device__ globals)
__device__ float g_rinv[B_ * H_ * L_];
__device__ __nv_bfloat16 g_qh[M_ * D_];
__device__ __nv_bfloat16 g_ql[M_ * D_];
__device__ __nv_bfloat16 g_kh[M_ * D_];
__device__ __nv_bfloat16 g_kl[M_ * D_];
__device__ __nv_bfloat16 g_vh[M_ * D_];
__device__ __nv_bfloat16 g_vl[M_ * D_];
__device__ __nv_bfloat16 g_ohh[M_ * D_];
__device__ __nv_bfloat16 g_ohl[M_ * D_];

// ===========================================================================
// Warp MMA m16n8k16 bf16 -> fp32 + ldmatrix (base PTX; assembles on sm_103)
// ===========================================================================
__device__ __forceinline__ void mma16816(float* d, const uint32_t* a,
                                         uint32_t b0, uint32_t b1,
                                         const float* c) {
  asm volatile(
      "mma.sync.aligned.m16n8k16.row.col.f32.bf16.bf16.f32 "
      "{%0,%1,%2,%3}, {%4,%5,%6,%7}, {%8,%9}, {%10,%11,%12,%13};"
      : "=f"(d[0]), "=f"(d[1]), "=f"(d[2]), "=f"(d[3])
      : "r"(a[0]), "r"(a[1]), "r"(a[2]), "r"(a[3]), "r"(b0), "r"(b1),
        "f"(c[0]), "f"(c[1]), "f"(c[2]), "f"(c[3]));
}
__device__ __forceinline__ void ldsm_x4(uint32_t* r, uint32_t addr) {
  asm volatile(
      "ldmatrix.sync.aligned.m8n8.x4.shared.b16 {%0,%1,%2,%3}, [%4];"
      : "=r"(r[0]), "=r"(r[1]), "=r"(r[2]), "=r"(r[3]) : "r"(addr));
}
__device__ __forceinline__ void ldsm_x4_t(uint32_t* r, uint32_t addr) {
  asm volatile(
      "ldmatrix.sync.aligned.m8n8.x4.trans.shared.b16 {%0,%1,%2,%3}, [%4];"
      : "=r"(r[0]), "=r"(r[1]), "=r"(r[2]), "=r"(r[3]) : "r"(addr));
}
__device__ __forceinline__ uint32_t smem_u32(const void* p) {
  uint32_t a;
  asm("{ .reg .u64 t; cvta.to.shared.u64 t, %1; cvt.u32.u64 %0, t; }"
      : "=r"(a) : "l"(p));
  return a;
}

// ===========================================================================
// Tensor-core GEMM: Y[M,N] = X[M,K] @ W[N,K]^T + bias, bf16x3 split precision.
// M=8192, N=K=512. Block 256 thr / 8 warps, tile 128(m) x 64(n), K-chunk 64.
// X: either fp32 (converted to hi/lo in the smem load) or preexisting bf16
// hi/lo arrays. Output: fp32 (Yf) or bf16 hi/lo split (Yh/Yl).
// ===========================================================================
#define GP 72  // padded row stride (bf16 elems); 144 B = 9*16, LDSM-clean

__global__ __launch_bounds__(256) void mma_gemm_kernel(
    const float* __restrict__ Xf,
    const __nv_bfloat16* __restrict__ Xh_g, const __nv_bfloat16* __restrict__ Xl_g,
    const float* __restrict__ W, const float* __restrict__ bias,
    float* __restrict__ Yf,
    __nv_bfloat16* __restrict__ Yh, __nv_bfloat16* __restrict__ Yl) {
  extern __shared__ __align__(16) char sm[];
  __nv_bfloat16* XH = (__nv_bfloat16*)(sm);             // [128][GP]
  __nv_bfloat16* XL = (__nv_bfloat16*)(sm + 18432);
  __nv_bfloat16* WH = (__nv_bfloat16*)(sm + 36864);     // [64][GP]
  __nv_bfloat16* WL = (__nv_bfloat16*)(sm + 46080);
  uint32_t sXH = smem_u32(XH), sXL = smem_u32(XL);
  uint32_t sWH = smem_u32(WH), sWL = smem_u32(WL);

  int tid = threadIdx.x, w = tid >> 5, lane = tid & 31;
  int gr = lane >> 2, ck = lane & 3;
  int bm = blockIdx.x * 128, bn = blockIdx.y * 64;

  // Per-lane ldsm offsets (bytes). A (row-major, non-trans):
  uint32_t aoff = (uint32_t)(((lane & 7) + ((lane >> 3) & 1) * 8) * GP +
                             ((lane >> 4) & 1) * 8) * 2;
  // B (col-major = natural [n][k], non-trans) — same pattern as attn K:
  uint32_t boff = (uint32_t)(((lane & 7) + ((lane >> 4) & 1) * 8) * GP +
                             ((lane >> 3) & 1) * 8) * 2;

  float Oa[8][4] = {};

  for (int k0 = 0; k0 < 512; k0 += 64) {
    __syncthreads();
    // --- X tile: 128 rows x 64 cols ---
    {
      int r = tid >> 1, c0 = (tid & 1) * 32;
      if (Xf) {
        const float4* src = (const float4*)&Xf[(size_t)(bm + r) * 512 + k0 + c0];
#pragma unroll
        for (int j = 0; j < 8; j++) {
          float4 v = src[j];
          __nv_bfloat162 h0, h1, l0, l1;
          h0.x = __float2bfloat16_rn(v.x); h0.y = __float2bfloat16_rn(v.y);
          h1.x = __float2bfloat16_rn(v.z); h1.y = __float2bfloat16_rn(v.w);
          l0.x = __float2bfloat16_rn(v.x - __bfloat162float(h0.x));
          l0.y = __float2bfloat16_rn(v.y - __bfloat162float(h0.y));
          l1.x = __float2bfloat16_rn(v.z - __bfloat162float(h1.x));
          l1.y = __float2bfloat16_rn(v.w - __bfloat162float(h1.y));
          int e = r * GP + c0 + 4 * j;
          *(__nv_bfloat162*)&XH[e] = h0; *(__nv_bfloat162*)&XH[e + 2] = h1;
          *(__nv_bfloat162*)&XL[e] = l0; *(__nv_bfloat162*)&XL[e + 2] = l1;
        }
      } else {
        const uint4* sh = (const uint4*)&Xh_g[(size_t)(bm + r) * 512 + k0 + c0];
        const uint4* sl = (const uint4*)&Xl_g[(size_t)(bm + r) * 512 + k0 + c0];
#pragma unroll
        for (int j = 0; j < 4; j++) {
          *(uint4*)&XH[r * GP + c0 + 8 * j] = sh[j];
          *(uint4*)&XL[r * GP + c0 + 8 * j] = sl[j];
        }
      }
    }
    // --- W tile: 64 rows x 64 cols ---
    {
      int r = tid >> 2, c0 = (tid & 3) * 16;
      const float4* src = (const float4*)&W[(size_t)(bn + r) * 512 + k0 + c0];
#pragma unroll
      for (int j = 0; j < 4; j++) {
        float4 v = src[j];
        __nv_bfloat162 h0, h1, l0, l1;
        h0.x = __float2bfloat16_rn(v.x); h0.y = __float2bfloat16_rn(v.y);
        h1.x = __float2bfloat16_rn(v.z); h1.y = __float2bfloat16_rn(v.w);
        l0.x = __float2bfloat16_rn(v.x - __bfloat162float(h0.x));
        l0.y = __float2bfloat16_rn(v.y - __bfloat162float(h0.y));
        l1.x = __float2bfloat16_rn(v.z - __bfloat162float(h1.x));
        l1.y = __float2bfloat16_rn(v.w - __bfloat162float(h1.y));
        int e = r * GP + c0 + 4 * j;
        *(__nv_bfloat162*)&WH[e] = h0; *(__nv_bfloat162*)&WH[e + 2] = h1;
        *(__nv_bfloat162*)&WL[e] = l0; *(__nv_bfloat162*)&WL[e + 2] = l1;
      }
    }
    __syncthreads();

#pragma unroll
    for (int kc = 0; kc < 4; kc++) {
      uint32_t abase = (uint32_t)((16 * w) * GP + 16 * kc) * 2 + aoff;
      uint32_t ah[4], al[4];
      ldsm_x4(ah, sXH + abase);
      ldsm_x4(al, sXL + abase);
#pragma unroll
      for (int ntp = 0; ntp < 4; ntp++) {
        uint32_t bbase = (uint32_t)((16 * ntp) * GP + 16 * kc) * 2 + boff;
        uint32_t bh4[4], bl4[4];
        ldsm_x4(bh4, sWH + bbase);
        ldsm_x4(bl4, sWL + bbase);
        mma16816(Oa[2 * ntp], ah, bh4[0], bh4[1], Oa[2 * ntp]);
        mma16816(Oa[2 * ntp + 1], ah, bh4[2], bh4[3], Oa[2 * ntp + 1]);
        mma16816(Oa[2 * ntp], ah, bl4[0], bl4[1], Oa[2 * ntp]);
        mma16816(Oa[2 * ntp + 1], ah, bl4[2], bl4[3], Oa[2 * ntp + 1]);
        mma16816(Oa[2 * ntp], al, bh4[0], bh4[1], Oa[2 * ntp]);
        mma16816(Oa[2 * ntp + 1], al, bh4[2], bh4[3], Oa[2 * ntp + 1]);
      }
    }
  }

  // Epilogue: bias + store (fp32 or bf16 hi/lo split)
  int row = bm + 16 * w + gr;
#pragma unroll
  for (int nt = 0; nt < 8; nt++) {
    int col = bn + 8 * nt + 2 * ck;
    float2 bb = *(const float2*)&bias[col];
    float o0 = Oa[nt][0] + bb.x, o1 = Oa[nt][1] + bb.y;
    float o2 = Oa[nt][2] + bb.x, o3 = Oa[nt][3] + bb.y;
    if (Yf) {
      *(float2*)&Yf[(size_t)row * 512 + col] = make_float2(o0, o1);
      *(float2*)&Yf[(size_t)(row + 8) * 512 + col] = make_float2(o2, o3);
    } else {
      __nv_bfloat162 h01 = __floats2bfloat162_rn(o0, o1);
      __nv_bfloat162 h23 = __floats2bfloat162_rn(o2, o3);
      __nv_bfloat162 l01 = __floats2bfloat162_rn(o0 - __bfloat162float(h01.x),
                                                 o1 - __bfloat162float(h01.y));
      __nv_bfloat162 l23 = __floats2bfloat162_rn(o2 - __bfloat162float(h23.x),
                                                 o3 - __bfloat162float(h23.y));
      *(__nv_bfloat162*)&Yh[(size_t)row * 512 + col] = h01;
      *(__nv_bfloat162*)&Yl[(size_t)row * 512 + col] = l01;
      *(__nv_bfloat162*)&Yh[(size_t)(row + 8) * 512 + col] = h23;
      *(__nv_bfloat162*)&Yl[(size_t)(row + 8) * 512 + col] = l23;
    }
  }
}

// ===========================================================================
// Warp-MMA attention (unchanged math from R9; epilogue now emits bf16 hi/lo O)
// ===========================================================================
#define PADK 72

__global__ __launch_bounds__(256) void attn_mma_kernel(
    const int* __restrict__ mask, float* __restrict__ attn_out, int has_attn) {
  __shared__ __nv_bfloat16 Ksh[64][PADK], Ksl[64][PADK];
  __shared__ __nv_bfloat16 Vsh[64][PADK], Vsl[64][PADK];
  __shared__ float maskS[64];

  int tid = threadIdx.x, w = tid >> 5, lane = tid & 31;
  int gr = lane >> 2, ck = lane & 3;
  int bh = blockIdx.y, b = bh >> 3, h = bh & 7;
  int q0 = blockIdx.x * 128;
  int qrow = b * L_ + q0 + 16 * w;

  int krow_l = (lane & 7) + ((lane >> 4) & 1) * 8;
  int kcol_l = ((lane >> 3) & 1) * 8;
  uint32_t koff = (uint32_t)(krow_l * PADK + kcol_l) * 2;
  int vrow_l = (lane & 7) + ((lane >> 3) & 1) * 8;
  int vcol_l = ((lane >> 4) & 1) * 8;
  uint32_t voff = (uint32_t)(vrow_l * PADK + vcol_l) * 2;

  uint32_t sKh = smem_u32(&Ksh[0][0]), sKl = smem_u32(&Ksl[0][0]);
  uint32_t sVh = smem_u32(&Vsh[0][0]), sVl = smem_u32(&Vsl[0][0]);

  uint32_t qh[4][4], ql[4][4];
#pragma unroll
  for (int kc = 0; kc < 4; kc++) {
    size_t r0 = (size_t)(qrow + gr) * D_ + h * DH_ + kc * 16 + 2 * ck;
    size_t r8 = r0 + (size_t)8 * D_;
    qh[kc][0] = *(const uint32_t*)(g_qh + r0);
    qh[kc][1] = *(const uint32_t*)(g_qh + r8);
    qh[kc][2] = *(const uint32_t*)(g_qh + r0 + 8);
    qh[kc][3] = *(const uint32_t*)(g_qh + r8 + 8);
    ql[kc][0] = *(const uint32_t*)(g_ql + r0);
    ql[kc][1] = *(const uint32_t*)(g_ql + r8);
    ql[kc][2] = *(const uint32_t*)(g_ql + r0 + 8);
    ql[kc][3] = *(const uint32_t*)(g_ql + r8 + 8);
  }

  float Oa[8][4] = {};
  float psum0 = 0.f, psum1 = 0.f;

  for (int kt = 0; kt < 32; kt++) {
    int k0 = kt * 64;
    __syncthreads();

    {
      int r = tid >> 2, c4 = (tid & 3) * 16;
      size_t gbase = (size_t)(b * L_ + k0 + r) * D_ + h * DH_ + c4;
      const uint4* p;
      p = (const uint4*)(g_kh + gbase);
      *(uint4*)&Ksh[r][c4] = p[0]; *(uint4*)&Ksh[r][c4 + 8] = p[1];
      p = (const uint4*)(g_kl + gbase);
      *(uint4*)&Ksl[r][c4] = p[0]; *(uint4*)&Ksl[r][c4 + 8] = p[1];
      p = (const uint4*)(g_vh + gbase);
      *(uint4*)&Vsh[r][c4] = p[0]; *(uint4*)&Vsh[r][c4 + 8] = p[1];
      p = (const uint4*)(g_vl + gbase);
      *(uint4*)&Vsl[r][c4] = p[0]; *(uint4*)&Vsl[r][c4 + 8] = p[1];
      if (tid < 64) maskS[tid] = -1e9f * (float)mask[b * L_ + k0 + tid];
    }
    __syncthreads();

    float Sa[8][4] = {};
#pragma unroll
    for (int kc = 0; kc < 4; kc++) {
#pragma unroll
      for (int ntp = 0; ntp < 4; ntp++) {
        uint32_t tb = (uint32_t)(16 * ntp * PADK + 16 * kc) * 2 + koff;
        uint32_t kh4[4], kl4[4];
        ldsm_x4(kh4, sKh + tb);
        ldsm_x4(kl4, sKl + tb);
        mma16816(Sa[2 * ntp], qh[kc], kh4[0], kh4[1], Sa[2 * ntp]);
        mma16816(Sa[2 * ntp + 1], qh[kc], kh4[2], kh4[3], Sa[2 * ntp + 1]);
        mma16816(Sa[2 * ntp], qh[kc], kl4[0], kl4[1], Sa[2 * ntp]);
        mma16816(Sa[2 * ntp + 1], qh[kc], kl4[2], kl4[3], Sa[2 * ntp + 1]);
        mma16816(Sa[2 * ntp], ql[kc], kh4[0], kh4[1], Sa[2 * ntp]);
        mma16816(Sa[2 * ntp + 1], ql[kc], kh4[2], kh4[3], Sa[2 * ntp + 1]);
      }
    }

#pragma unroll
    for (int nt = 0; nt < 8; nt++) {
      float2 mk = *(float2*)&maskS[8 * nt + 2 * ck];
      float p0 = __expf(fmaf(Sa[nt][0], 0.125f, mk.x));
      float p1 = __expf(fmaf(Sa[nt][1], 0.125f, mk.y));
      float p2 = __expf(fmaf(Sa[nt][2], 0.125f, mk.x));
      float p3 = __expf(fmaf(Sa[nt][3], 0.125f, mk.y));
      psum0 += p0 + p1; psum1 += p2 + p3;
      Sa[nt][0] = p0; Sa[nt][1] = p1; Sa[nt][2] = p2; Sa[nt][3] = p3;
      if (has_attn) {
        size_t base = (size_t)(bh * L_ + q0 + 16 * w + gr) * L_ + k0 + 8 * nt + 2 * ck;
        *(float2*)&attn_out[base] = make_float2(p0, p1);
        *(float2*)&attn_out[base + (size_t)8 * L_] = make_float2(p2, p3);
      }
    }

#pragma unroll
    for (int kc = 0; kc < 4; kc++) {
      uint32_t ph[4], pl[4];
#pragma unroll
      for (int half = 0; half < 2; half++) {
        float x0 = Sa[2 * kc + half][0], x1 = Sa[2 * kc + half][1];
        float x2 = Sa[2 * kc + half][2], x3 = Sa[2 * kc + half][3];
        __nv_bfloat162 h01 = __floats2bfloat162_rn(x0, x1);
        __nv_bfloat162 h23 = __floats2bfloat162_rn(x2, x3);
        __nv_bfloat162 l01 = __floats2bfloat162_rn(x0 - __bfloat162float(h01.x),
                                                   x1 - __bfloat162float(h01.y));
        __nv_bfloat162 l23 = __floats2bfloat162_rn(x2 - __bfloat162float(h23.x),
                                                   x3 - __bfloat162float(h23.y));
        ph[2 * half + 0] = *(uint32_t*)&h01; ph[2 * half + 1] = *(uint32_t*)&h23;
        pl[2 * half + 0] = *(uint32_t*)&l01; pl[2 * half + 1] = *(uint32_t*)&l23;
      }
#pragma unroll
      for (int ntp = 0; ntp < 4; ntp++) {
        uint32_t tb = (uint32_t)(16 * kc * PADK + 16 * ntp) * 2 + voff;
        uint32_t vh4[4], vl4[4];
        ldsm_x4_t(vh4, sVh + tb);
        ldsm_x4_t(vl4, sVl + tb);
        mma16816(Oa[2 * ntp], ph, vh4[0], vh4[1], Oa[2 * ntp]);
        mma16816(Oa[2 * ntp + 1], ph, vh4[2], vh4[3], Oa[2 * ntp + 1]);
        mma16816(Oa[2 * ntp], ph, vl4[0], vl4[1], Oa[2 * ntp]);
        mma16816(Oa[2 * ntp + 1], ph, vl4[2], vl4[3], Oa[2 * ntp + 1]);
        mma16816(Oa[2 * ntp], pl, vh4[0], vh4[1], Oa[2 * ntp]);
        mma16816(Oa[2 * ntp + 1], pl, vh4[2], vh4[3], Oa[2 * ntp + 1]);
      }
    }
  }

  psum0 += __shfl_xor_sync(0xFFFFFFFF, psum0, 1);
  psum0 += __shfl_xor_sync(0xFFFFFFFF, psum0, 2);
  psum1 += __shfl_xor_sync(0xFFFFFFFF, psum1, 1);
  psum1 += __shfl_xor_sync(0xFFFFFFFF, psum1, 2);
  float inv0 = 1.0f / psum0, inv1 = 1.0f / psum1;
  if (ck == 0) {
    g_rinv[(size_t)bh * L_ + q0 + 16 * w + gr] = inv0;
    g_rinv[(size_t)bh * L_ + q0 + 16 * w + gr + 8] = inv1;
  }

  // O store: scaled, bf16 hi/lo split (feeds the MMA output GEMM directly)
#pragma unroll
  for (int nt = 0; nt < 8; nt++) {
    size_t base = (size_t)(b * L_ + q0 + 16 * w + gr) * D_ + h * DH_ + 8 * nt + 2 * ck;
    float o0 = Oa[nt][0] * inv0, o1 = Oa[nt][1] * inv0;
    float o2 = Oa[nt][2] * inv1, o3 = Oa[nt][3] * inv1;
    __nv_bfloat162 h01 = __floats2bfloat162_rn(o0, o1);
    __nv_bfloat162 h23 = __floats2bfloat162_rn(o2, o3);
    __nv_bfloat162 l01 = __floats2bfloat162_rn(o0 - __bfloat162float(h01.x),
                                               o1 - __bfloat162float(h01.y));
    __nv_bfloat162 l23 = __floats2bfloat162_rn(o2 - __bfloat162float(h23.x),
                                               o3 - __bfloat162float(h23.y));
    *(__nv_bfloat162*)&g_ohh[base] = h01;
    *(__nv_bfloat162*)&g_ohl[base] = l01;
    *(__nv_bfloat162*)&g_ohh[base + (size_t)8 * D_] = h23;
    *(__nv_bfloat162*)&g_ohl[base + (size_t)8 * D_] = l23;
  }
}

// ---------------------------------------------------------------------------
// Normalize attn in place: attn[row, :] *= g_rinv[row]
// ---------------------------------------------------------------------------
__global__ __launch_bounds__(256) void norm_attn_kernel(float* __restrict__ attn) {
  size_t idx = ((size_t)blockIdx.x * 256 + threadIdx.x) * 4;
  size_t row = idx >> 11;
  float inv = g_rinv[row];
  float4 v = *(float4*)&attn[idx];
  v.x *= inv; v.y *= inv; v.z *= inv; v.w *= inv;
  *(float4*)&attn[idx] = v;
}

// ---------------------------------------------------------------------------
extern "C" void kernel_launch(void* const* d_in, const int* in_sizes, int n_in,
                              void* d_out, int out_size) {
  const float* q    = (const float*)d_in[0];
  const float* k    = (const float*)d_in[1];
  const float* v    = (const float*)d_in[2];
  const int*   mask = (const int*)d_in[3];
  const float* wq_w = (const float*)d_in[4];
  const float* wq_b = (const float*)d_in[5];
  const float* wk_w = (const float*)d_in[6];
  const float* wk_b = (const float*)d_in[7];
  const float* wv_w = (const float*)d_in[8];
  const float* wv_b = (const float*)d_in[9];
  const float* wo_w = (const float*)d_in[10];
  const float* wo_b = (const float*)d_in[11];
  float* out = (float*)d_out;

  const long long OUT_N  = (long long)M_ * D_;
  const long long ATTN_N = (long long)B_ * H_ * L_ * L_;
  int has_attn = ((long long)out_size >= OUT_N + ATTN_N) ? 1 : 0;
  float* attn = out + OUT_N;

  void *p_qh, *p_ql, *p_kh, *p_kl, *p_vh, *p_vl, *p_ohh, *p_ohl;
  cudaGetSymbolAddress(&p_qh, g_qh);
  cudaGetSymbolAddress(&p_ql, g_ql);
  cudaGetSymbolAddress(&p_kh, g_kh);
  cudaGetSymbolAddress(&p_kl, g_kl);
  cudaGetSymbolAddress(&p_vh, g_vh);
  cudaGetSymbolAddress(&p_vl, g_vl);
  cudaGetSymbolAddress(&p_ohh, g_ohh);
  cudaGetSymbolAddress(&p_ohl, g_ohl);

  const int GS = 55296;  // dynamic smem for mma_gemm_kernel
  cudaFuncSetAttribute(mma_gemm_kernel,
                       cudaFuncAttributeMaxDynamicSharedMemorySize, GS);
  dim3 gp(M_ / 128, D_ / 64);

  mma_gemm_kernel<<<gp, 256, GS>>>(q, nullptr, nullptr, wq_w, wq_b, nullptr,
                                   (__nv_bfloat16*)p_qh, (__nv_bfloat16*)p_ql);
  mma_gemm_kernel<<<gp, 256, GS>>>(k, nullptr, nullptr, wk_w, wk_b, nullptr,
                                   (__nv_bfloat16*)p_kh, (__nv_bfloat16*)p_kl);
  mma_gemm_kernel<<<gp, 256, GS>>>(v, nullptr, nullptr, wv_w, wv_b, nullptr,
                                   (__nv_bfloat16*)p_vh, (__nv_bfloat16*)p_vl);

  dim3 ga(L_ / 128, B_ * H_);
  attn_mma_kernel<<<ga, 256>>>(mask, attn, has_attn);

  if (has_attn) {
    norm_attn_kernel<<<(unsigned)(ATTN_N / 4 / 256), 256>>>(attn);
  }

  mma_gemm_kernel<<<gp, 256, GS>>>(nullptr, (const __nv_bfloat16*)p_ohh,
                                   (const __nv_bfloat16*)p_ohl, wo_w, wo_b, out,
                                   nullptr, nullptr);
}